// round 16
// baseline (speedup 1.0000x reference)
#include <cuda_runtime.h>
#include <stdint.h>

#define NB 64
#define NC 768
#define NN 576
#define NG 3
#define GS 192
#define NT 1024
#define NWP 32
#define TCH 32                       // channels per tile
#define TILES 24                     // tiles per pass
#define TBYTES (TCH * NN * 4)        // 73728

// dynamic smem offsets (bytes)
#define BUF0_OFF  0
#define BUF1_OFF  73728
#define TREE_OFF  147456             // 8*288 float2 = 18432
#define HEAT_OFF  165888             // 576 f32
#define TOTS_OFF  168192             // 768 f32
#define SLAB_OFF  171264             // 576 u8
#define RED_OFF   171840             // 32 f32
#define MBAR_OFF  171968             // 2 x u64
#define FLG_OFF   171984
#define SMEM_SZ   172032

__device__ float g_gsum[2 * NB * NG * NC];
__device__ float g_partial[NB];
__device__ int   g_pair[NB];         // self-resetting
__device__ int   g_counter;          // self-resetting

__device__ __forceinline__ uint32_t smem_u32(const void* p) {
    uint32_t a;
    asm("{ .reg .u64 t; cvta.to.shared.u64 t, %1; cvt.u32.u64 %0, t; }" : "=r"(a) : "l"(p));
    return a;
}
#define MBAR_INIT(a, c) \
    asm volatile("mbarrier.init.shared.b64 [%0], %1;" :: "r"(a), "r"(c) : "memory")
#define MBAR_EXPECT(a, bytes) \
    asm volatile("mbarrier.arrive.expect_tx.shared.b64 _, [%0], %1;" :: "r"(a), "r"(bytes) : "memory")
#define BULK_CP(dst, src, bytes, bar) \
    asm volatile("cp.async.bulk.shared::cluster.global.mbarrier::complete_tx::bytes [%0], [%1], %2, [%3];" \
                 :: "r"(dst), "l"(src), "r"(bytes), "r"(bar) : "memory")
#define MBAR_WAIT(bar, ph) do {                                              \
    asm volatile(                                                            \
        "{\n\t.reg .pred P1;\n\t"                                            \
        "WL_%=:\n\t"                                                         \
        "mbarrier.try_wait.parity.acquire.cta.shared::cta.b64 P1, [%0], %1, 0x989680;\n\t" \
        "@P1 bra.uni WD_%=;\n\t"                                             \
        "bra.uni WL_%=;\n\t"                                                 \
        "WD_%=:\n\t}"                                                        \
        :: "r"(bar), "r"(ph) : "memory");                                    \
} while (0)

__device__ __forceinline__ float block_reduce(float v, float* red) {
    const int lane = threadIdx.x & 31, w = threadIdx.x >> 5;
#pragma unroll
    for (int o = 16; o; o >>= 1) v += __shfl_down_sync(0xffffffffu, v, o);
    if (lane == 0) red[w] = v;
    __syncthreads();
    if (threadIdx.x < 32) {
        v = red[threadIdx.x];
#pragma unroll
        for (int o = 16; o; o >>= 1) v += __shfl_down_sync(0xffffffffu, v, o);
        if (threadIdx.x == 0) red[0] = v;
    }
    __syncthreads();
    float r = red[0];
    __syncthreads();
    return r;
}

// ---------------------------------------------------------------------------
// One CTA per (img,b). 48 tiles (2 passes x 24) via cp.async.bulk double
// buffer; warps consume from SMEM. Rank between tile 23 and 24 overlaps the
// already-issued pass-2 copies. Inline pairing epilogue.
// ---------------------------------------------------------------------------
__global__ __launch_bounds__(NT, 1)
void fused_tma(const float* __restrict__ in0, const float* __restrict__ in1,
               float* __restrict__ out) {
    extern __shared__ char smem[];
    float*         bufs[2] = { (float*)(smem + BUF0_OFF), (float*)(smem + BUF1_OFF) };
    float2*        tree  = (float2*)(smem + TREE_OFF);
    float*         heatC = (float*)(smem + HEAT_OFF);
    float*         tots  = (float*)(smem + TOTS_OFF);
    unsigned char* slab  = (unsigned char*)(smem + SLAB_OFF);
    float*         red   = (float*)(smem + RED_OFF);
    int*           flg   = (int*)(smem + FLG_OFF);
    const uint32_t mb[2] = { smem_u32(smem + MBAR_OFF), smem_u32(smem + MBAR_OFF + 8) };
    const uint32_t sb[2] = { smem_u32(smem + BUF0_OFF), smem_u32(smem + BUF1_OFF) };

    const int ib   = blockIdx.x;              // img*NB + b
    const int b    = ib & (NB - 1);
    const float* src = ((ib >= NB) ? in1 : in0) + (size_t)b * NC * NN;

    const int tid  = threadIdx.x;
    const int w    = tid >> 5;                // 0..31
    const int lane = tid & 31;

    if (tid == 0) { MBAR_INIT(mb[0], 1); MBAR_INIT(mb[1], 1); }
    __syncthreads();

    if (tid == 0) {
        MBAR_EXPECT(mb[0], TBYTES);
        BULK_CP(sb[0], src + 0 * TCH * NN, TBYTES, mb[0]);
        MBAR_EXPECT(mb[1], TBYTES);
        BULK_CP(sb[1], src + 1 * TCH * NN, TBYTES, mb[1]);
    }

    float2 acc[9];
#pragma unroll
    for (int j = 0; j < 9; ++j) acc[j] = make_float2(0.f, 0.f);
    unsigned bm0 = 0, bm1 = 0;
    int cnt[2] = { 0, 0 };

    for (int t = 0; t < 2 * TILES; ++t) {
        const int bi = t & 1;
        MBAR_WAIT(mb[bi], cnt[bi] & 1);
        cnt[bi]++;

        const int tc  = (t < TILES) ? t : (t - TILES);   // tile index in pass
        const int c   = tc * TCH + w;                    // this warp's channel
        const float2* row = (const float2*)(bufs[bi] + (size_t)w * NN);

        if (t < TILES) {
            // ---- pass 1: heat partials + channel total
            float ts = 0.f;
#pragma unroll
            for (int j = 0; j < 9; ++j) {
                float2 v = row[lane + 32 * j];
                acc[j].x += v.x;
                acc[j].y += v.y;
                ts += v.x + v.y;
            }
#pragma unroll
            for (int o = 16; o; o >>= 1) ts += __shfl_down_sync(0xffffffffu, ts, o);
            if (lane == 0) tots[c] = ts;
        } else {
            // ---- pass 2: masked group sums from SMEM
            float s0 = 0.f, s1 = 0.f;
#pragma unroll
            for (int j = 0; j < 9; ++j) {
                float2 v = row[lane + 32 * j];
                if ((bm0 >> (2 * j)) & 1u)     s0 += v.x;
                if ((bm0 >> (2 * j + 1)) & 1u) s0 += v.y;
                if ((bm1 >> (2 * j)) & 1u)     s1 += v.x;
                if ((bm1 >> (2 * j + 1)) & 1u) s1 += v.y;
            }
#pragma unroll
            for (int o = 16; o; o >>= 1) {
                s0 += __shfl_down_sync(0xffffffffu, s0, o);
                s1 += __shfl_down_sync(0xffffffffu, s1, o);
            }
            if (lane == 0) {
                float* dst = g_gsum + (size_t)ib * NG * NC;
                dst[c]          = s0;
                dst[NC + c]     = s1;
                dst[2 * NC + c] = tots[c] - s0 - s1;   // 1/192 cancels in norm
            }
        }
        __syncthreads();   // everyone done with buffer bi

        if (tid == 0 && t + 2 < 2 * TILES) {
            const int nt  = t + 2;
            const int ntc = (nt < TILES) ? nt : (nt - TILES);
            MBAR_EXPECT(mb[bi], TBYTES);
            BULK_CP(sb[bi], src + (size_t)ntc * TCH * NN, TBYTES, mb[bi]);
        }

        if (t == TILES - 1) {
            // ===== tree combine -> heat; rank; bitmasks (pass-2 copies in flight)
            if (w >= 8 && w < 16) {
#pragma unroll
                for (int j = 0; j < 9; ++j) tree[(w - 8) * 288 + lane + 32 * j] = acc[j];
            }
            __syncthreads();
            if (w < 8) {
#pragma unroll
                for (int j = 0; j < 9; ++j) {
                    float2 tv = tree[w * 288 + lane + 32 * j];
                    acc[j].x += tv.x; acc[j].y += tv.y;
                }
            }
            __syncthreads();
            if (w >= 16 && w < 24) {
#pragma unroll
                for (int j = 0; j < 9; ++j) tree[(w - 16) * 288 + lane + 32 * j] = acc[j];
            }
            __syncthreads();
            if (w < 8) {
#pragma unroll
                for (int j = 0; j < 9; ++j) {
                    float2 tv = tree[w * 288 + lane + 32 * j];
                    acc[j].x += tv.x; acc[j].y += tv.y;
                }
            }
            __syncthreads();
            if (w >= 24) {
#pragma unroll
                for (int j = 0; j < 9; ++j) tree[(w - 24) * 288 + lane + 32 * j] = acc[j];
            }
            __syncthreads();
            if (w < 8) {
#pragma unroll
                for (int j = 0; j < 9; ++j) {
                    float2 tv = tree[w * 288 + lane + 32 * j];
                    acc[j].x += tv.x; acc[j].y += tv.y;
                }
            }
            __syncthreads();
            if (w >= 1 && w < 8) {
#pragma unroll
                for (int j = 0; j < 9; ++j) tree[(w - 1) * 288 + lane + 32 * j] = acc[j];
            }
            __syncthreads();
            if (w == 0) {
#pragma unroll
                for (int s = 0; s < 7; ++s) {
#pragma unroll
                    for (int j = 0; j < 9; ++j) {
                        float2 tv = tree[s * 288 + lane + 32 * j];
                        acc[j].x += tv.x; acc[j].y += tv.y;
                    }
                }
#pragma unroll
                for (int j = 0; j < 9; ++j)
                    ((float2*)heatC)[lane + 32 * j] = acc[j];
            }
            __syncthreads();

            // rank + tercile label: warp w owns n in [18w, 18w+18)
            {
                float kr[18];
#pragma unroll
                for (int j = 0; j < 18; ++j) kr[j] = heatC[lane + 32 * j];
#pragma unroll
                for (int i = 0; i < 18; ++i) {
                    int n = 18 * w + i;
                    float hn = heatC[n];
                    unsigned cntc = 0;
#pragma unroll
                    for (int j = 0; j < 18; ++j) {
                        int m = lane + 32 * j;
                        cntc += (kr[j] > hn) || (kr[j] == hn && m < n);
                    }
                    unsigned rk = __reduce_add_sync(0xffffffffu, cntc);
                    if (lane == 0) slab[n] = (unsigned char)(rk / GS);
                }
            }
            __syncthreads();

#pragma unroll
            for (int j = 0; j < 9; ++j) {
                int n = 2 * (lane + 32 * j);
                unsigned char l0 = slab[n], l1 = slab[n + 1];
                bm0 |= ((l0 == 0) ? 1u : 0u) << (2 * j);
                bm0 |= ((l1 == 0) ? 1u : 0u) << (2 * j + 1);
                bm1 |= ((l0 == 1) ? 1u : 0u) << (2 * j);
                bm1 |= ((l1 == 1) ? 1u : 0u) << (2 * j + 1);
            }
        }
    }
    __syncthreads();

    // ---- Pairing: second CTA of this b computes normalize + SSD
    if (tid == 0) {
        __threadfence();
        int prev = atomicAdd(&g_pair[b], 1);
        if (prev == 1) { g_pair[b] = 0; *flg = 1; }   // self-reset for replay
        else           { *flg = 0; }
    }
    __syncthreads();
    if (!*flg) return;
    __threadfence();

    const float* v1 = g_gsum + (size_t)b * NG * NC;
    const float* v2 = g_gsum + (size_t)(NB + b) * NG * NC;

    float ss1 = 0.f, ss2 = 0.f;
    for (int i = tid; i < NG * NC; i += NT) {
        float a = v1[i], c = v2[i];
        ss1 = fmaf(a, a, ss1);
        ss2 = fmaf(c, c, ss2);
    }
    ss1 = block_reduce(ss1, red);
    ss2 = block_reduce(ss2, red);
    float i1 = 1.f / fmaxf(sqrtf(ss1), 1e-12f);
    float i2 = 1.f / fmaxf(sqrtf(ss2), 1e-12f);

    float acc2 = 0.f;
    for (int i = tid; i < NG * NC; i += NT) {
        float d = v1[i] * i1 - v2[i] * i2;
        acc2 = fmaf(d, d, acc2);
    }
    acc2 = block_reduce(acc2, red);

    if (tid == 0) {
        g_partial[b] = acc2;
        __threadfence();
        int prev = atomicAdd(&g_counter, 1);
        if (prev == NB - 1) { g_counter = 0; *flg = 1; }
        else                { *flg = 0; }
    }
    __syncthreads();

    if (*flg && tid < 32) {
        float v = g_partial[tid] + g_partial[tid + 32];
#pragma unroll
        for (int o = 16; o; o >>= 1) v += __shfl_down_sync(0xffffffffu, v, o);
        if (tid == 0) out[0] = v * (1.f / (float)(NB * NG * NC));
    }
}

extern "C" void kernel_launch(void* const* d_in, const int* in_sizes, int n_in,
                              void* d_out, int out_size) {
    const float* in0 = (const float*)d_in[0];
    const float* in1 = (const float*)d_in[1];
    float* out = (float*)d_out;
    (void)in_sizes; (void)n_in; (void)out_size;

    cudaFuncSetAttribute(fused_tma, cudaFuncAttributeMaxDynamicSharedMemorySize, SMEM_SZ);
    fused_tma<<<2 * NB, NT, SMEM_SZ>>>(in0, in1, out);
}

// round 17
// speedup vs baseline: 1.0870x; 1.0870x over previous
#include <cuda_runtime.h>
#include <stdint.h>

#define NB 64
#define NC 768
#define NN 576
#define NG 3
#define GS 192
#define HC 384               // channels per half-chunk
#define NW 16                // warps per 512-thr CTA

__device__ float         g_heatP[2 * NB * 2 * NW * NN]; // [chunk][half][warp][576]
__device__ float         g_tots [2 * NB * NC];          // [chunk][c]
__device__ unsigned char g_slab [2 * NB * NN];          // [chunk][n] labels
__device__ float         g_gsum [2 * NB * NG * NC];     // [chunk][3*NC]
__device__ float         g_partial[NB];
__device__ int           g_done[NB];                    // 4 CTAs per b (self-reset)
__device__ int           g_counter;                     // 64 epilogues (self-reset)

// ---------------------------------------------------------------------------
// K1: PURE STREAM. 256 CTAs x 512 thr (2/SM). Half-chunk each. Heat partials
// in regs; per-channel totals via shfl; one coalesced partial dump at end.
// ---------------------------------------------------------------------------
__global__ __launch_bounds__(512, 2)
void heat_k(const float* __restrict__ in0, const float* __restrict__ in1) {
    const int id    = blockIdx.x;              // 0..255
    const int chunk = id >> 1;                 // img*64 + b
    const int h     = id & 1;
    const int b     = chunk & (NB - 1);
    const float* src = ((chunk >= NB) ? in1 : in0)
                     + ((size_t)b * NC + (size_t)h * HC) * NN;

    const int w    = threadIdx.x >> 5;         // 0..15
    const int lane = threadIdx.x & 31;

    float2 acc[9];
#pragma unroll
    for (int j = 0; j < 9; ++j) acc[j] = make_float2(0.f, 0.f);

    float* tdst = g_tots + (size_t)chunk * NC + (size_t)h * HC;
#pragma unroll 2
    for (int k = 0; k < HC / NW; ++k) {        // 24 channels per warp
        const int c = w + NW * k;
        const float2* row = (const float2*)(src + (size_t)c * NN);
        float2 v[9];
#pragma unroll
        for (int j = 0; j < 9; ++j) v[j] = row[lane + 32 * j];
        float t = 0.f;
#pragma unroll
        for (int j = 0; j < 9; ++j) {
            acc[j].x += v[j].x;
            acc[j].y += v[j].y;
            t += v[j].x + v[j].y;
        }
#pragma unroll
        for (int o = 16; o; o >>= 1) t += __shfl_down_sync(0xffffffffu, t, o);
        if (lane == 0) tdst[c] = t;
    }

    float2* hp = (float2*)(g_heatP + (((size_t)chunk * 2 + h) * NW + w) * NN);
#pragma unroll
    for (int j = 0; j < 9; ++j) hp[lane + 32 * j] = acc[j];
}

// ---------------------------------------------------------------------------
// K1.5: combine 32 partials in fixed order -> rank -> write labels. Tiny.
// ---------------------------------------------------------------------------
__global__ __launch_bounds__(1024, 1)
void label_k() {
    __shared__ float heatC[NN];
    const int chunk = blockIdx.x;
    const int tid   = threadIdx.x;
    const int w     = tid >> 5;                // 0..31
    const int lane  = tid & 31;

    if (tid < NN) {
        const float* hp = g_heatP + (size_t)chunk * 32 * NN + tid;
        float hsum = 0.f;
#pragma unroll
        for (int s = 0; s < 32; ++s) hsum += hp[s * NN];
        heatC[tid] = hsum;
    }
    __syncthreads();

    {
        float kr[18];
#pragma unroll
        for (int j = 0; j < 18; ++j) kr[j] = heatC[lane + 32 * j];
#pragma unroll
        for (int i = 0; i < 18; ++i) {
            int n = 18 * w + i;
            float hn = heatC[n];
            unsigned cnt = 0;
#pragma unroll
            for (int j = 0; j < 18; ++j) {
                int m = lane + 32 * j;
                cnt += (kr[j] > hn) || (kr[j] == hn && m < n);
            }
            unsigned rk = __reduce_add_sync(0xffffffffu, cnt);
            if (lane == 0) g_slab[(size_t)chunk * NN + n] = (unsigned char)(rk / GS);
        }
    }
}

__device__ __forceinline__ float block_reduce512(float v, float* red) {
    const int lane = threadIdx.x & 31, w = threadIdx.x >> 5;
#pragma unroll
    for (int o = 16; o; o >>= 1) v += __shfl_down_sync(0xffffffffu, v, o);
    if (lane == 0) red[w] = v;
    __syncthreads();
    if (threadIdx.x < 16) {
        v = red[threadIdx.x];
#pragma unroll
        for (int o = 8; o; o >>= 1) v += __shfl_down_sync(0x0000ffffu, v, o);
        if (threadIdx.x == 0) red[0] = v;
    }
    __syncthreads();
    float r = red[0];
    __syncthreads();
    return r;
}

// ---------------------------------------------------------------------------
// K2: PURE STREAM masked sums. 256 CTAs x 512 thr. Labels from global (L2),
// stream half-chunk, s2 = tot - s0 - s1. Inline pairing epilogue (4 per b).
// ---------------------------------------------------------------------------
__global__ __launch_bounds__(512, 2)
void gsum_k(const float* __restrict__ in0, const float* __restrict__ in1,
            float* __restrict__ out) {
    __shared__ unsigned char slab[NN];
    __shared__ float         red[NW];
    __shared__ int           flg;

    const int id    = blockIdx.x;              // 0..255
    const int chunk = id >> 1;
    const int h     = id & 1;
    const int b     = chunk & (NB - 1);
    const float* src = ((chunk >= NB) ? in1 : in0)
                     + ((size_t)b * NC + (size_t)h * HC) * NN;

    const int tid  = threadIdx.x;
    const int w    = tid >> 5;
    const int lane = tid & 31;

    if (tid < NN / 4)
        ((uint32_t*)slab)[tid] =
            ((const uint32_t*)(g_slab + (size_t)chunk * NN))[tid];
    __syncthreads();

    unsigned bm0 = 0, bm1 = 0;
#pragma unroll
    for (int j = 0; j < 9; ++j) {
        int n = 2 * (lane + 32 * j);
        unsigned char l0 = slab[n], l1 = slab[n + 1];
        bm0 |= ((l0 == 0) ? 1u : 0u) << (2 * j);
        bm0 |= ((l1 == 0) ? 1u : 0u) << (2 * j + 1);
        bm1 |= ((l0 == 1) ? 1u : 0u) << (2 * j);
        bm1 |= ((l1 == 1) ? 1u : 0u) << (2 * j + 1);
    }

    const float* tsrc = g_tots + (size_t)chunk * NC + (size_t)h * HC;
    float* dst = g_gsum + (size_t)chunk * NG * NC + (size_t)h * HC;
#pragma unroll 2
    for (int k = 0; k < HC / NW; ++k) {
        const int c = w + NW * k;
        const float2* row = (const float2*)(src + (size_t)c * NN);
        float s0 = 0.f, s1 = 0.f;
#pragma unroll
        for (int j = 0; j < 9; ++j) {
            float2 v = row[lane + 32 * j];
            if ((bm0 >> (2 * j)) & 1u)     s0 += v.x;
            if ((bm0 >> (2 * j + 1)) & 1u) s0 += v.y;
            if ((bm1 >> (2 * j)) & 1u)     s1 += v.x;
            if ((bm1 >> (2 * j + 1)) & 1u) s1 += v.y;
        }
#pragma unroll
        for (int o = 16; o; o >>= 1) {
            s0 += __shfl_down_sync(0xffffffffu, s0, o);
            s1 += __shfl_down_sync(0xffffffffu, s1, o);
        }
        if (lane == 0) {
            dst[c]          = s0;
            dst[NC + c]     = s1;
            dst[2 * NC + c] = tsrc[c] - s0 - s1;   // 1/192 cancels in L2 norm
        }
    }
    __syncthreads();

    // ---- Pairing: 4th CTA of this b (2 img x 2 halves) computes SSD
    if (tid == 0) {
        __threadfence();
        int prev = atomicAdd(&g_done[b], 1);
        if (prev == 3) { g_done[b] = 0; flg = 1; }   // self-reset for replay
        else           { flg = 0; }
    }
    __syncthreads();
    if (!flg) return;
    __threadfence();

    const float* v1 = g_gsum + (size_t)b * NG * NC;
    const float* v2 = g_gsum + (size_t)(NB + b) * NG * NC;

    float ss1 = 0.f, ss2 = 0.f;
    for (int i = tid; i < NG * NC; i += 512) {
        float a = v1[i], c = v2[i];
        ss1 = fmaf(a, a, ss1);
        ss2 = fmaf(c, c, ss2);
    }
    ss1 = block_reduce512(ss1, red);
    ss2 = block_reduce512(ss2, red);
    float i1 = 1.f / fmaxf(sqrtf(ss1), 1e-12f);
    float i2 = 1.f / fmaxf(sqrtf(ss2), 1e-12f);

    float acc2 = 0.f;
    for (int i = tid; i < NG * NC; i += 512) {
        float d = v1[i] * i1 - v2[i] * i2;
        acc2 = fmaf(d, d, acc2);
    }
    acc2 = block_reduce512(acc2, red);

    if (tid == 0) {
        g_partial[b] = acc2;
        __threadfence();
        int prev = atomicAdd(&g_counter, 1);
        if (prev == NB - 1) { g_counter = 0; flg = 1; }
        else                { flg = 0; }
    }
    __syncthreads();

    if (flg && tid < 32) {
        float v = g_partial[tid] + g_partial[tid + 32];
#pragma unroll
        for (int o = 16; o; o >>= 1) v += __shfl_down_sync(0xffffffffu, v, o);
        if (tid == 0) out[0] = v * (1.f / (float)(NB * NG * NC));
    }
}

extern "C" void kernel_launch(void* const* d_in, const int* in_sizes, int n_in,
                              void* d_out, int out_size) {
    const float* in0 = (const float*)d_in[0];
    const float* in1 = (const float*)d_in[1];
    float* out = (float*)d_out;
    (void)in_sizes; (void)n_in; (void)out_size;

    heat_k <<<4 * NB, 512>>>(in0, in1);
    label_k<<<2 * NB, 1024>>>();
    gsum_k <<<4 * NB, 512>>>(in0, in1, out);
}